// round 9
// baseline (speedup 1.0000x reference)
#include <cuda_runtime.h>
#include <cuda_fp16.h>
#include <cstdint>

#define B_ 16
#define L_ 2048
#define D_ 128
#define MT 128             // query rows per work item (32 per warp)
#define NT 32              // keys per tile
#define NTILES 64
#define MTILES 16          // L_/MT
#define NITEMS (B_ * MTILES)   // 256
#define TOT (B_ * L_ * D_)

#define STRB 272           // fp16 tile row stride in BYTES (128 elems + 8 pad)

// smem byte offsets
#define SM_Q16   0         // 128 rows x 272B = 34816 (reused as rowsum after loop)
#define SM_STAGE 34816     // four stages follow
#define STG_K    0
#define STG_V    8704
#define STG_BYTES 17408
#define SMEM_BYTES (SM_STAGE + 4 * STG_BYTES)   // 104448 (2 CTAs/SM)

// ---- preconverted fp16 scratch + unnormalized-probs fp16 scratch ----
__device__ __align__(16) static uint32_t g_k16[TOT / 2];
__device__ __align__(16) static uint32_t g_v16[TOT / 2];
__device__ __align__(16) static uint32_t g_pscr[(B_ * L_ / 2) * L_];  // 134MB

__device__ __forceinline__ uint32_t smem_u32(const void* p) {
    uint32_t a;
    asm("{ .reg .u64 t; cvta.to.shared.u64 t, %1; cvt.u32.u64 %0, t; }" : "=r"(a) : "l"(p));
    return a;
}

#define CP16(SA, GA) \
    asm volatile("cp.async.cg.shared.global [%0], [%1], 16;" :: "r"(SA), "l"(GA) : "memory")
#define CP_COMMIT() asm volatile("cp.async.commit_group;" ::: "memory")
#define CP_WAIT(N)  asm volatile("cp.async.wait_group %0;" :: "n"(N) : "memory")

#define LDSM4(R0, R1, R2, R3, ADDR) \
    asm volatile("ldmatrix.sync.aligned.m8n8.x4.shared.b16 {%0,%1,%2,%3}, [%4];" \
        : "=r"(R0), "=r"(R1), "=r"(R2), "=r"(R3) : "r"(ADDR))

#define LDSM4T(R0, R1, R2, R3, ADDR) \
    asm volatile("ldmatrix.sync.aligned.m8n8.x4.trans.shared.b16 {%0,%1,%2,%3}, [%4];" \
        : "=r"(R0), "=r"(R1), "=r"(R2), "=r"(R3) : "r"(ADDR))

#define MMA_F16(D, A0, A1, A2, A3, B0, B1) \
    asm volatile("mma.sync.aligned.m16n8k16.row.col.f32.f16.f16.f32 " \
        "{%0,%1,%2,%3}, {%4,%5,%6,%7}, {%8,%9}, {%0,%1,%2,%3};" \
        : "+f"((D)[0]), "+f"((D)[1]), "+f"((D)[2]), "+f"((D)[3]) \
        : "r"(A0), "r"(A1), "r"(A2), "r"(A3), "r"(B0), "r"(B1))

__device__ __forceinline__ uint32_t pack_h2(float x0, float x1) {
    __half h0 = __float2half_rn(x0);
    __half h1 = __float2half_rn(x1);
    return (uint32_t)__half_as_ushort(h0) | ((uint32_t)__half_as_ushort(h1) << 16);
}

// ============================================================================
// Kernel 0: convert K and V to fp16 scratch (~9us, DRAM-bound)
// ============================================================================
__global__ void __launch_bounds__(256)
split_kv_kernel(const float* __restrict__ k, const float* __restrict__ v)
{
    const size_t i4 = (size_t)blockIdx.x * 256 + threadIdx.x;
    const float4 kx = ((const float4*)k)[i4];
    const float4 vx = ((const float4*)v)[i4];
    uint2 kh, vh;
    kh.x = pack_h2(kx.x, kx.y);  kh.y = pack_h2(kx.z, kx.w);
    vh.x = pack_h2(vx.x, vx.y);  vh.y = pack_h2(vx.z, vx.w);
    ((uint2*)g_k16)[i4] = kh;
    ((uint2*)g_v16)[i4] = vh;
}

// prefetch one 32-key tile (K16,V16): 512 chunks x 2 tensors, 8/thread
__device__ __forceinline__ void prefetch_tile(uint32_t st_base, size_t gelem, int t)
{
    const unsigned long long kg = (unsigned long long)__cvta_generic_to_global(g_k16);
    const unsigned long long vg = (unsigned long long)__cvta_generic_to_global(g_v16);
    #pragma unroll
    for (int j = 0; j < 4; ++j) {
        const int c   = t + j * 128;              // 0..511
        const int row = c >> 4;
        const int col = c & 15;
        const uint32_t so = (uint32_t)row * STRB + (uint32_t)col * 16;
        const unsigned long long go = ((unsigned long long)(gelem + (size_t)row * D_) + col * 8) * 2;
        CP16(st_base + STG_K + so, kg + go);
        CP16(st_base + STG_V + so, vg + go);
    }
}

// ============================================================================
// Kernel 1: 256 CTAs (128 threads, occ 2), item = (batch, 128 q-rows),
// 32 rows per warp. fp16 GEMMs: S = Q16*K16, ctx += P16*V16.
// 4-stage cp.async pipeline. Unnormalized p written fp16 to scratch;
// fused epilogue normalizes into fp32 probs (no separate norm kernel).
// ============================================================================
__global__ void __launch_bounds__(128, 2)
attn_mma_kernel(const float* __restrict__ q,
                float* __restrict__ ctx,
                float* __restrict__ probs)
{
    extern __shared__ char smem[];
    const uint32_t sb = smem_u32(smem);
    const uint32_t Q16 = sb + SM_Q16;
    float* rsum_sm = (float*)smem;     // reused after the main loop

    const int t   = threadIdx.x;
    const int wid = t >> 5;            // 0..3
    const int lid = t & 31;

    const float SL = 0.08838834764831845f * 1.4426950408889634f; // scale*log2(e)

    // ldmatrix per-lane base offsets (bytes); warp owns rows [32*wid, 32*wid+32)
    const uint32_t q_off0 = (uint32_t)(wid * 32 + (lid & 15)) * STRB + (uint32_t)(lid >> 4) * 16;
    const uint32_t q_off1 = q_off0 + 16u * STRB;
    const uint32_t k_off  = (uint32_t)((lid & 7) + ((lid >> 4) << 3)) * STRB
                          + (uint32_t)((lid >> 3) & 1) * 16;
    const uint32_t v_off  = (uint32_t)((lid & 7) + (((lid >> 3) & 1) << 3)) * STRB
                          + (uint32_t)(lid >> 4) * 16;

    const int item   = (int)blockIdx.x;
    const int b      = item >> 4;
    const int m_base = (item & 15) * MT;
    const size_t bL  = (size_t)b * L_;
    const float* qb  = q + (bL + m_base) * D_;
    const size_t kvb = bL * D_;

    // stagger tile order across CTAs to decorrelate load phases
    const int start = (int)((blockIdx.x & 3u) << 4);   // 0,16,32,48

    // prologue: prefetch 3 tiles
    #pragma unroll
    for (int pi = 0; pi < 3; ++pi) {
        const int ptile = (start + pi) & (NTILES - 1);
        prefetch_tile(sb + SM_STAGE + (uint32_t)pi * STG_BYTES,
                      kvb + (size_t)(ptile * NT) * D_, t);
        CP_COMMIT();
    }

    // ---- load + convert Q tile (128x128) to fp16: one row per thread ----
    {
        const float4* src = (const float4*)(qb + (size_t)t * D_);
        char* dh = smem + SM_Q16 + t * STRB;
        #pragma unroll
        for (int cc = 0; cc < 16; ++cc) {
            const float4 x0 = src[2 * cc];
            const float4 x1 = src[2 * cc + 1];
            uint4 H;
            H.x = pack_h2(x0.x, x0.y);
            H.y = pack_h2(x0.z, x0.w);
            H.z = pack_h2(x1.x, x1.y);
            H.w = pack_h2(x1.z, x1.w);
            *(uint4*)(dh + cc * 16) = H;
        }
    }

    float C[2][16][4];
    #pragma unroll
    for (int mf = 0; mf < 2; ++mf)
        #pragma unroll
        for (int f = 0; f < 16; ++f)
            #pragma unroll
            for (int e = 0; e < 4; ++e) C[mf][f][e] = 0.0f;
    float rs[2][2] = {{0.f, 0.f}, {0.f, 0.f}};

    for (int i = 0; i < NTILES; ++i) {
        const int tile = (start + i) & (NTILES - 1);
        const int key0 = tile * NT;
        const uint32_t stg = sb + SM_STAGE + (uint32_t)(i & 3) * STG_BYTES;

        __syncthreads();

        if (i + 3 < NTILES) {
            const int ntile = (start + i + 3) & (NTILES - 1);
            prefetch_tile(sb + SM_STAGE + (uint32_t)((i + 3) & 3) * STG_BYTES,
                          kvb + (size_t)(ntile * NT) * D_, t);
        }
        CP_COMMIT();
        CP_WAIT(3);
        __syncthreads();

        const uint32_t KHI = stg + STG_K;
        const uint32_t VHI = stg + STG_V;

        // ---- QK: S = Q16*K16, 2 m-frags per warp ----
        float S[2][4][4];
        #pragma unroll
        for (int mf = 0; mf < 2; ++mf)
            #pragma unroll
            for (int f = 0; f < 4; ++f)
                #pragma unroll
                for (int e = 0; e < 4; ++e) S[mf][f][e] = 0.0f;

        #pragma unroll
        for (int ks = 0; ks < 8; ++ks) {
            uint32_t a0[4], a1[4], bh[8];
            LDSM4(a0[0], a0[1], a0[2], a0[3], Q16 + q_off0 + ks * 32);
            LDSM4(a1[0], a1[1], a1[2], a1[3], Q16 + q_off1 + ks * 32);
            #pragma unroll
            for (int j = 0; j < 2; ++j)
                LDSM4(bh[4*j], bh[4*j+1], bh[4*j+2], bh[4*j+3],
                      KHI + k_off + (uint32_t)j * (16 * STRB) + ks * 32);
            #pragma unroll
            for (int j = 0; j < 2; ++j) {
                MMA_F16(S[0][2*j],   a0[0], a0[1], a0[2], a0[3], bh[4*j],   bh[4*j+1]);
                MMA_F16(S[0][2*j+1], a0[0], a0[1], a0[2], a0[3], bh[4*j+2], bh[4*j+3]);
                MMA_F16(S[1][2*j],   a1[0], a1[1], a1[2], a1[3], bh[4*j],   bh[4*j+1]);
                MMA_F16(S[1][2*j+1], a1[0], a1[1], a1[2], a1[3], bh[4*j+2], bh[4*j+3]);
            }
        }

        // ---- exp + fp16 scratch write + pack P16 A-frags (per m-frag) ----
        uint32_t PH[2][2][4];
        #pragma unroll
        for (int mf = 0; mf < 2; ++mf) {
            uint32_t* prow = g_pscr
                + (((size_t)(bL + m_base + 32 * wid + 16 * mf + (lid >> 2))) * L_
                   + key0 + 2 * (lid & 3)) / 2;
            #pragma unroll
            for (int f = 0; f < 4; ++f) {
                const float p0 = exp2f(S[mf][f][0] * SL);
                const float p1 = exp2f(S[mf][f][1] * SL);
                const float p2 = exp2f(S[mf][f][2] * SL);
                const float p3 = exp2f(S[mf][f][3] * SL);
                rs[mf][0] += p0 + p1;
                rs[mf][1] += p2 + p3;
                const int ks = f >> 1;
                const int hh = (f & 1) * 2;
                PH[mf][ks][hh]     = pack_h2(p0, p1);
                PH[mf][ks][hh + 1] = pack_h2(p2, p3);
                prow[4 * f]            = PH[mf][ks][hh];      // row r,   cols 8f+..
                prow[4 * L_ + 4 * f]   = PH[mf][ks][hh + 1];  // row r+8 (8*L_/2)
            }
        }

        // ---- PV: ctx += P16*V16 ----
        #pragma unroll
        for (int ks = 0; ks < 2; ++ks) {
            uint32_t vf[32];
            #pragma unroll
            for (int j = 0; j < 8; ++j)
                LDSM4T(vf[4*j], vf[4*j+1], vf[4*j+2], vf[4*j+3],
                       VHI + v_off + (uint32_t)ks * (16 * STRB) + j * 32);
            #pragma unroll
            for (int j = 0; j < 8; ++j) {
                MMA_F16(C[0][2*j],   PH[0][ks][0], PH[0][ks][1], PH[0][ks][2], PH[0][ks][3], vf[4*j],   vf[4*j+1]);
                MMA_F16(C[0][2*j+1], PH[0][ks][0], PH[0][ks][1], PH[0][ks][2], PH[0][ks][3], vf[4*j+2], vf[4*j+3]);
                MMA_F16(C[1][2*j],   PH[1][ks][0], PH[1][ks][1], PH[1][ks][2], PH[1][ks][3], vf[4*j],   vf[4*j+1]);
                MMA_F16(C[1][2*j+1], PH[1][ks][0], PH[1][ks][1], PH[1][ks][2], PH[1][ks][3], vf[4*j+2], vf[4*j+3]);
            }
        }
    }

    __syncthreads();   // done with Q16 smem; reuse as rowsum storage

    // ---- row sums + normalize + store ctx, per m-frag; stash inv in smem ----
    #pragma unroll
    for (int mf = 0; mf < 2; ++mf) {
        float r0 = rs[mf][0], r1 = rs[mf][1];
        r0 += __shfl_xor_sync(0xffffffffu, r0, 1);
        r0 += __shfl_xor_sync(0xffffffffu, r0, 2);
        r1 += __shfl_xor_sync(0xffffffffu, r1, 1);
        r1 += __shfl_xor_sync(0xffffffffu, r1, 2);
        const float inv0 = 1.0f / r0;
        const float inv1 = 1.0f / r1;

        if ((lid & 3) == 0) {
            rsum_sm[32 * wid + 16 * mf + (lid >> 2)]     = inv0;
            rsum_sm[32 * wid + 16 * mf + (lid >> 2) + 8] = inv1;
        }

        float* crow = ctx
            + ((size_t)(bL + m_base + 32 * wid + 16 * mf + (lid >> 2))) * D_
            + 2 * (lid & 3);
        #pragma unroll
        for (int f = 0; f < 16; ++f) {
            *(float2*)(crow + 8 * f)          = make_float2(C[mf][f][0] * inv0, C[mf][f][1] * inv0);
            *(float2*)(crow + 8 * D_ + 8 * f) = make_float2(C[mf][f][2] * inv1, C[mf][f][3] * inv1);
        }
    }
    __syncthreads();

    // ---- epilogue: normalize own 128 probs rows (fp16 scratch -> fp32 out) ----
    {
        const uint32_t* src = g_pscr + ((size_t)(bL + m_base) * L_) / 2;
        float* dst = probs + (size_t)(bL + m_base) * L_;
        #pragma unroll 4
        for (int kk = 0; kk < 256; ++kk) {
            const int idx = t + kk * 128;       // 0..32767
            const int row = idx >> 8;           // 0..127
            const int cc  = idx & 255;          // uint4 chunk within row
            const float inv = rsum_sm[row];
            const uint4 d = *(const uint4*)(src + (size_t)row * (L_ / 2) + cc * 4);
            float* drow = dst + (size_t)row * L_ + cc * 8;
            float2 f0 = __half22float2(*(const __half2*)&d.x);
            float2 f1 = __half22float2(*(const __half2*)&d.y);
            float2 f2 = __half22float2(*(const __half2*)&d.z);
            float2 f3 = __half22float2(*(const __half2*)&d.w);
            float4 o0, o1;
            o0.x = f0.x * inv; o0.y = f0.y * inv; o0.z = f1.x * inv; o0.w = f1.y * inv;
            o1.x = f2.x * inv; o1.y = f2.y * inv; o1.z = f3.x * inv; o1.w = f3.y * inv;
            *(float4*)(drow)     = o0;
            *(float4*)(drow + 4) = o1;
        }
    }
}

extern "C" void kernel_launch(void* const* d_in, const int* in_sizes, int n_in,
                              void* d_out, int out_size)
{
    const float* q = (const float*)d_in[0];
    const float* k = (const float*)d_in[1];
    const float* v = (const float*)d_in[2];

    float* out   = (float*)d_out;
    float* ctx   = out;
    float* probs = out + (size_t)B_ * L_ * D_;

    cudaFuncSetAttribute(attn_mma_kernel,
                         cudaFuncAttributeMaxDynamicSharedMemorySize, SMEM_BYTES);

    split_kv_kernel<<<TOT / 4 / 256, 256>>>(k, v);

    attn_mma_kernel<<<NITEMS, 128, SMEM_BYTES>>>(q, ctx, probs);
}

// round 10
// speedup vs baseline: 1.4218x; 1.4218x over previous
#include <cuda_runtime.h>
#include <cuda_fp16.h>
#include <cstdint>

#define B_ 16
#define L_ 2048
#define D_ 128
#define MT 128             // query rows per work item (32 per warp)
#define NT 32              // keys per tile
#define NTILES 64
#define MTILES 16          // L_/MT
#define NITEMS (B_ * MTILES)   // 256
#define TOT (B_ * L_ * D_)

#define STRB 272           // fp16 tile row stride in BYTES (128 elems + 8 pad)

// smem byte offsets
#define SM_Q16   0         // 128 rows x 272B = 34816
#define SM_STAGE 34816     // four stages follow
#define STG_K    0
#define STG_V    8704
#define STG_BYTES 17408
#define SMEM_BYTES (SM_STAGE + 4 * STG_BYTES)   // 104448 (2 CTAs/SM)

// ---- device scratch ----
__device__ __align__(16) static uint32_t g_k16[TOT / 2];
__device__ __align__(16) static uint32_t g_v16[TOT / 2];
__device__ __align__(16) static uint32_t g_pscr[(B_ * L_ / 2) * L_];  // fp16 unnorm p, 134MB
__device__ __align__(16) static float    g_inv[B_ * L_];              // per-row 1/sum

__device__ __forceinline__ uint32_t smem_u32(const void* p) {
    uint32_t a;
    asm("{ .reg .u64 t; cvta.to.shared.u64 t, %1; cvt.u32.u64 %0, t; }" : "=r"(a) : "l"(p));
    return a;
}

#define CP16(SA, GA) \
    asm volatile("cp.async.cg.shared.global [%0], [%1], 16;" :: "r"(SA), "l"(GA) : "memory")
#define CP_COMMIT() asm volatile("cp.async.commit_group;" ::: "memory")
#define CP_WAIT(N)  asm volatile("cp.async.wait_group %0;" :: "n"(N) : "memory")

#define LDSM4(R0, R1, R2, R3, ADDR) \
    asm volatile("ldmatrix.sync.aligned.m8n8.x4.shared.b16 {%0,%1,%2,%3}, [%4];" \
        : "=r"(R0), "=r"(R1), "=r"(R2), "=r"(R3) : "r"(ADDR))

#define LDSM4T(R0, R1, R2, R3, ADDR) \
    asm volatile("ldmatrix.sync.aligned.m8n8.x4.trans.shared.b16 {%0,%1,%2,%3}, [%4];" \
        : "=r"(R0), "=r"(R1), "=r"(R2), "=r"(R3) : "r"(ADDR))

#define MMA_F16(D, A0, A1, A2, A3, B0, B1) \
    asm volatile("mma.sync.aligned.m16n8k16.row.col.f32.f16.f16.f32 " \
        "{%0,%1,%2,%3}, {%4,%5,%6,%7}, {%8,%9}, {%0,%1,%2,%3};" \
        : "+f"((D)[0]), "+f"((D)[1]), "+f"((D)[2]), "+f"((D)[3]) \
        : "r"(A0), "r"(A1), "r"(A2), "r"(A3), "r"(B0), "r"(B1))

__device__ __forceinline__ uint32_t pack_h2(float x0, float x1) {
    __half h0 = __float2half_rn(x0);
    __half h1 = __float2half_rn(x1);
    return (uint32_t)__half_as_ushort(h0) | ((uint32_t)__half_as_ushort(h1) << 16);
}

// ============================================================================
// Kernel 0: convert K and V to fp16 scratch (~9us, DRAM-bound)
// ============================================================================
__global__ void __launch_bounds__(256)
split_kv_kernel(const float* __restrict__ k, const float* __restrict__ v)
{
    const size_t i4 = (size_t)blockIdx.x * 256 + threadIdx.x;
    const float4 kx = ((const float4*)k)[i4];
    const float4 vx = ((const float4*)v)[i4];
    uint2 kh, vh;
    kh.x = pack_h2(kx.x, kx.y);  kh.y = pack_h2(kx.z, kx.w);
    vh.x = pack_h2(vx.x, vx.y);  vh.y = pack_h2(vx.z, vx.w);
    ((uint2*)g_k16)[i4] = kh;
    ((uint2*)g_v16)[i4] = vh;
}

// prefetch one 32-key tile (K16,V16): 512 chunks x 2 tensors, 8/thread
__device__ __forceinline__ void prefetch_tile(uint32_t st_base, size_t gelem, int t)
{
    const unsigned long long kg = (unsigned long long)__cvta_generic_to_global(g_k16);
    const unsigned long long vg = (unsigned long long)__cvta_generic_to_global(g_v16);
    #pragma unroll
    for (int j = 0; j < 4; ++j) {
        const int c   = t + j * 128;              // 0..511
        const int row = c >> 4;
        const int col = c & 15;
        const uint32_t so = (uint32_t)row * STRB + (uint32_t)col * 16;
        const unsigned long long go = ((unsigned long long)(gelem + (size_t)row * D_) + col * 8) * 2;
        CP16(st_base + STG_K + so, kg + go);
        CP16(st_base + STG_V + so, vg + go);
    }
}

// ============================================================================
// Kernel 1: 256 CTAs (128 threads, occ 2), item = (batch, 128 q-rows),
// 32 rows per warp. fp16 GEMMs: S = Q16*K16, ctx += P16*V16.
// 4-stage cp.async pipeline. Writes fp16 unnormalized p to scratch and
// per-row inverse sums; norm kernel finishes probs.
// ============================================================================
__global__ void __launch_bounds__(128, 2)
attn_mma_kernel(const float* __restrict__ q,
                float* __restrict__ ctx)
{
    extern __shared__ char smem[];
    const uint32_t sb = smem_u32(smem);
    const uint32_t Q16 = sb + SM_Q16;

    const int t   = threadIdx.x;
    const int wid = t >> 5;            // 0..3
    const int lid = t & 31;

    const float SL = 0.08838834764831845f * 1.4426950408889634f; // scale*log2(e)

    // ldmatrix per-lane base offsets (bytes); warp owns rows [32*wid, 32*wid+32)
    const uint32_t q_off0 = (uint32_t)(wid * 32 + (lid & 15)) * STRB + (uint32_t)(lid >> 4) * 16;
    const uint32_t q_off1 = q_off0 + 16u * STRB;
    const uint32_t k_off  = (uint32_t)((lid & 7) + ((lid >> 4) << 3)) * STRB
                          + (uint32_t)((lid >> 3) & 1) * 16;
    const uint32_t v_off  = (uint32_t)((lid & 7) + (((lid >> 3) & 1) << 3)) * STRB
                          + (uint32_t)(lid >> 4) * 16;

    const int item   = (int)blockIdx.x;
    const int b      = item >> 4;
    const int m_base = (item & 15) * MT;
    const size_t bL  = (size_t)b * L_;
    const float* qb  = q + (bL + m_base) * D_;
    const size_t kvb = bL * D_;

    // stagger tile order across CTAs to decorrelate load phases
    const int start = (int)((blockIdx.x & 3u) << 4);   // 0,16,32,48

    // prologue: prefetch 3 tiles
    #pragma unroll
    for (int pi = 0; pi < 3; ++pi) {
        const int ptile = (start + pi) & (NTILES - 1);
        prefetch_tile(sb + SM_STAGE + (uint32_t)pi * STG_BYTES,
                      kvb + (size_t)(ptile * NT) * D_, t);
        CP_COMMIT();
    }

    // ---- load + convert Q tile (128x128) to fp16: one row per thread ----
    {
        const float4* src = (const float4*)(qb + (size_t)t * D_);
        char* dh = smem + SM_Q16 + t * STRB;
        #pragma unroll
        for (int cc = 0; cc < 16; ++cc) {
            const float4 x0 = src[2 * cc];
            const float4 x1 = src[2 * cc + 1];
            uint4 H;
            H.x = pack_h2(x0.x, x0.y);
            H.y = pack_h2(x0.z, x0.w);
            H.z = pack_h2(x1.x, x1.y);
            H.w = pack_h2(x1.z, x1.w);
            *(uint4*)(dh + cc * 16) = H;
        }
    }

    float C[2][16][4];
    #pragma unroll
    for (int mf = 0; mf < 2; ++mf)
        #pragma unroll
        for (int f = 0; f < 16; ++f)
            #pragma unroll
            for (int e = 0; e < 4; ++e) C[mf][f][e] = 0.0f;
    float rs[2][2] = {{0.f, 0.f}, {0.f, 0.f}};

    for (int i = 0; i < NTILES; ++i) {
        const int tile = (start + i) & (NTILES - 1);
        const int key0 = tile * NT;
        const uint32_t stg = sb + SM_STAGE + (uint32_t)(i & 3) * STG_BYTES;

        __syncthreads();

        if (i + 3 < NTILES) {
            const int ntile = (start + i + 3) & (NTILES - 1);
            prefetch_tile(sb + SM_STAGE + (uint32_t)((i + 3) & 3) * STG_BYTES,
                          kvb + (size_t)(ntile * NT) * D_, t);
        }
        CP_COMMIT();
        CP_WAIT(3);
        __syncthreads();

        const uint32_t KHI = stg + STG_K;
        const uint32_t VHI = stg + STG_V;

        // ---- QK: S = Q16*K16, 2 m-frags per warp ----
        float S[2][4][4];
        #pragma unroll
        for (int mf = 0; mf < 2; ++mf)
            #pragma unroll
            for (int f = 0; f < 4; ++f)
                #pragma unroll
                for (int e = 0; e < 4; ++e) S[mf][f][e] = 0.0f;

        #pragma unroll
        for (int ks = 0; ks < 8; ++ks) {
            uint32_t a0[4], a1[4], bh[8];
            LDSM4(a0[0], a0[1], a0[2], a0[3], Q16 + q_off0 + ks * 32);
            LDSM4(a1[0], a1[1], a1[2], a1[3], Q16 + q_off1 + ks * 32);
            #pragma unroll
            for (int j = 0; j < 2; ++j)
                LDSM4(bh[4*j], bh[4*j+1], bh[4*j+2], bh[4*j+3],
                      KHI + k_off + (uint32_t)j * (16 * STRB) + ks * 32);
            #pragma unroll
            for (int j = 0; j < 2; ++j) {
                MMA_F16(S[0][2*j],   a0[0], a0[1], a0[2], a0[3], bh[4*j],   bh[4*j+1]);
                MMA_F16(S[0][2*j+1], a0[0], a0[1], a0[2], a0[3], bh[4*j+2], bh[4*j+3]);
                MMA_F16(S[1][2*j],   a1[0], a1[1], a1[2], a1[3], bh[4*j],   bh[4*j+1]);
                MMA_F16(S[1][2*j+1], a1[0], a1[1], a1[2], a1[3], bh[4*j+2], bh[4*j+3]);
            }
        }

        // ---- exp + fp16 scratch write + pack P16 A-frags (per m-frag) ----
        uint32_t PH[2][2][4];
        #pragma unroll
        for (int mf = 0; mf < 2; ++mf) {
            uint32_t* prow = g_pscr
                + (((size_t)(bL + m_base + 32 * wid + 16 * mf + (lid >> 2))) * L_
                   + key0 + 2 * (lid & 3)) / 2;
            #pragma unroll
            for (int f = 0; f < 4; ++f) {
                const float p0 = exp2f(S[mf][f][0] * SL);
                const float p1 = exp2f(S[mf][f][1] * SL);
                const float p2 = exp2f(S[mf][f][2] * SL);
                const float p3 = exp2f(S[mf][f][3] * SL);
                rs[mf][0] += p0 + p1;
                rs[mf][1] += p2 + p3;
                const int ks = f >> 1;
                const int hh = (f & 1) * 2;
                PH[mf][ks][hh]     = pack_h2(p0, p1);
                PH[mf][ks][hh + 1] = pack_h2(p2, p3);
                prow[4 * f]          = PH[mf][ks][hh];      // row r
                prow[4 * L_ + 4 * f] = PH[mf][ks][hh + 1];  // row r+8
            }
        }

        // ---- PV: ctx += P16*V16 ----
        #pragma unroll
        for (int ks = 0; ks < 2; ++ks) {
            uint32_t vf[32];
            #pragma unroll
            for (int j = 0; j < 8; ++j)
                LDSM4T(vf[4*j], vf[4*j+1], vf[4*j+2], vf[4*j+3],
                       VHI + v_off + (uint32_t)ks * (16 * STRB) + j * 32);
            #pragma unroll
            for (int j = 0; j < 8; ++j) {
                MMA_F16(C[0][2*j],   PH[0][ks][0], PH[0][ks][1], PH[0][ks][2], PH[0][ks][3], vf[4*j],   vf[4*j+1]);
                MMA_F16(C[0][2*j+1], PH[0][ks][0], PH[0][ks][1], PH[0][ks][2], PH[0][ks][3], vf[4*j+2], vf[4*j+3]);
                MMA_F16(C[1][2*j],   PH[1][ks][0], PH[1][ks][1], PH[1][ks][2], PH[1][ks][3], vf[4*j],   vf[4*j+1]);
                MMA_F16(C[1][2*j+1], PH[1][ks][0], PH[1][ks][1], PH[1][ks][2], PH[1][ks][3], vf[4*j+2], vf[4*j+3]);
            }
        }
    }

    // ---- row sums + normalize ctx + store inv sums ----
    #pragma unroll
    for (int mf = 0; mf < 2; ++mf) {
        float r0 = rs[mf][0], r1 = rs[mf][1];
        r0 += __shfl_xor_sync(0xffffffffu, r0, 1);
        r0 += __shfl_xor_sync(0xffffffffu, r0, 2);
        r1 += __shfl_xor_sync(0xffffffffu, r1, 1);
        r1 += __shfl_xor_sync(0xffffffffu, r1, 2);
        const float inv0 = 1.0f / r0;
        const float inv1 = 1.0f / r1;

        const int row0 = m_base + 32 * wid + 16 * mf + (lid >> 2);
        if ((lid & 3) == 0) {
            g_inv[bL + row0]     = inv0;
            g_inv[bL + row0 + 8] = inv1;
        }

        float* crow = ctx + ((size_t)(bL + row0)) * D_ + 2 * (lid & 3);
        #pragma unroll
        for (int f = 0; f < 16; ++f) {
            *(float2*)(crow + 8 * f)          = make_float2(C[mf][f][0] * inv0, C[mf][f][1] * inv0);
            *(float2*)(crow + 8 * D_ + 8 * f) = make_float2(C[mf][f][2] * inv1, C[mf][f][3] * inv1);
        }
    }
}

// ============================================================================
// Kernel 2: streaming normalize: probs = fp16_scratch * inv[row] -> fp32.
// Pure streaming (no sum pass): 402MB total -> ~57us at 80% roofline.
// ============================================================================
__global__ void __launch_bounds__(256)
norm_probs_kernel(float* __restrict__ probs)
{
    const size_t rowi = blockIdx.x;
    const int t = threadIdx.x;
    const float inv = g_inv[rowi];

    const uint4 d = ((const uint4*)(g_pscr + rowi * (L_ / 2)))[t];
    float2 f0 = __half22float2(*(const __half2*)&d.x);
    float2 f1 = __half22float2(*(const __half2*)&d.y);
    float2 f2 = __half22float2(*(const __half2*)&d.z);
    float2 f3 = __half22float2(*(const __half2*)&d.w);

    float4 o0, o1;
    o0.x = f0.x * inv; o0.y = f0.y * inv; o0.z = f1.x * inv; o0.w = f1.y * inv;
    o1.x = f2.x * inv; o1.y = f2.y * inv; o1.z = f3.x * inv; o1.w = f3.y * inv;

    float* drow = probs + rowi * (size_t)L_ + t * 8;
    *(float4*)(drow)     = o0;
    *(float4*)(drow + 4) = o1;
}

extern "C" void kernel_launch(void* const* d_in, const int* in_sizes, int n_in,
                              void* d_out, int out_size)
{
    const float* q = (const float*)d_in[0];
    const float* k = (const float*)d_in[1];
    const float* v = (const float*)d_in[2];

    float* out   = (float*)d_out;
    float* ctx   = out;
    float* probs = out + (size_t)B_ * L_ * D_;

    cudaFuncSetAttribute(attn_mma_kernel,
                         cudaFuncAttributeMaxDynamicSharedMemorySize, SMEM_BYTES);

    split_kv_kernel<<<TOT / 4 / 256, 256>>>(k, v);

    attn_mma_kernel<<<NITEMS, 128, SMEM_BYTES>>>(q, ctx);

    norm_probs_kernel<<<B_ * L_, 256>>>(probs);
}

// round 11
// speedup vs baseline: 1.4982x; 1.0537x over previous
#include <cuda_runtime.h>
#include <cuda_fp16.h>
#include <cstdint>

#define B_ 16
#define L_ 2048
#define D_ 128
#define MT 128             // query rows per work item (32 per warp)
#define NT 32              // keys per tile
#define NTILES 64
#define MTILES 16          // L_/MT
#define NITEMS (B_ * MTILES)   // 256
#define TOT (B_ * L_ * D_)

#define STRB 272           // fp16 tile row stride in BYTES (128 elems + 8 pad)

// smem byte offsets
#define SM_Q16   0         // 128 rows x 272B = 34816
#define SM_STAGE 34816     // four stages follow
#define STG_K    0
#define STG_V    8704
#define STG_BYTES 17408
#define SMEM_BYTES (SM_STAGE + 4 * STG_BYTES)   // 104448 (2 CTAs/SM)

// ---- device scratch ----
__device__ __align__(16) static uint32_t g_k16[TOT / 2];
__device__ __align__(16) static uint32_t g_v16[TOT / 2];
__device__ __align__(16) static uint32_t g_pscr[(B_ * L_ / 2) * L_];  // fp16 unnorm p, 134MB
__device__ __align__(16) static float    g_inv[B_ * L_];              // per-row 1/sum

__device__ __forceinline__ uint32_t smem_u32(const void* p) {
    uint32_t a;
    asm("{ .reg .u64 t; cvta.to.shared.u64 t, %1; cvt.u32.u64 %0, t; }" : "=r"(a) : "l"(p));
    return a;
}

#define CP16(SA, GA) \
    asm volatile("cp.async.cg.shared.global [%0], [%1], 16;" :: "r"(SA), "l"(GA) : "memory")
#define CP_COMMIT() asm volatile("cp.async.commit_group;" ::: "memory")
#define CP_WAIT(N)  asm volatile("cp.async.wait_group %0;" :: "n"(N) : "memory")

#define LDSM4(R0, R1, R2, R3, ADDR) \
    asm volatile("ldmatrix.sync.aligned.m8n8.x4.shared.b16 {%0,%1,%2,%3}, [%4];" \
        : "=r"(R0), "=r"(R1), "=r"(R2), "=r"(R3) : "r"(ADDR))

#define LDSM4T(R0, R1, R2, R3, ADDR) \
    asm volatile("ldmatrix.sync.aligned.m8n8.x4.trans.shared.b16 {%0,%1,%2,%3}, [%4];" \
        : "=r"(R0), "=r"(R1), "=r"(R2), "=r"(R3) : "r"(ADDR))

#define MMA_F16(D, A0, A1, A2, A3, B0, B1) \
    asm volatile("mma.sync.aligned.m16n8k16.row.col.f32.f16.f16.f32 " \
        "{%0,%1,%2,%3}, {%4,%5,%6,%7}, {%8,%9}, {%0,%1,%2,%3};" \
        : "+f"((D)[0]), "+f"((D)[1]), "+f"((D)[2]), "+f"((D)[3]) \
        : "r"(A0), "r"(A1), "r"(A2), "r"(A3), "r"(B0), "r"(B1))

// single-MUFU exp2
__device__ __forceinline__ float ex2(float x) {
    float r;
    asm("ex2.approx.f32 %0, %1;" : "=f"(r) : "f"(x));
    return r;
}
// single-instruction fp32x2 -> fp16x2 pack (x0 -> low half)
__device__ __forceinline__ uint32_t cvt_h2(float x0, float x1) {
    uint32_t d;
    asm("cvt.rn.f16x2.f32 %0, %1, %2;" : "=r"(d) : "f"(x1), "f"(x0));
    return d;
}

// ============================================================================
// Kernel 0: convert K and V to fp16 scratch (~9us, DRAM-bound)
// ============================================================================
__global__ void __launch_bounds__(256)
split_kv_kernel(const float* __restrict__ k, const float* __restrict__ v)
{
    const size_t i4 = (size_t)blockIdx.x * 256 + threadIdx.x;
    const float4 kx = ((const float4*)k)[i4];
    const float4 vx = ((const float4*)v)[i4];
    uint2 kh, vh;
    kh.x = cvt_h2(kx.x, kx.y);  kh.y = cvt_h2(kx.z, kx.w);
    vh.x = cvt_h2(vx.x, vx.y);  vh.y = cvt_h2(vx.z, vx.w);
    ((uint2*)g_k16)[i4] = kh;
    ((uint2*)g_v16)[i4] = vh;
}

// prefetch one 32-key tile (K16,V16): 512 chunks x 2 tensors, 8/thread
__device__ __forceinline__ void prefetch_tile(uint32_t st_base, size_t gelem, int t)
{
    const unsigned long long kg = (unsigned long long)__cvta_generic_to_global(g_k16);
    const unsigned long long vg = (unsigned long long)__cvta_generic_to_global(g_v16);
    #pragma unroll
    for (int j = 0; j < 4; ++j) {
        const int c   = t + j * 128;              // 0..511
        const int row = c >> 4;
        const int col = c & 15;
        const uint32_t so = (uint32_t)row * STRB + (uint32_t)col * 16;
        const unsigned long long go = ((unsigned long long)(gelem + (size_t)row * D_) + col * 8) * 2;
        CP16(st_base + STG_K + so, kg + go);
        CP16(st_base + STG_V + so, vg + go);
    }
}

// ============================================================================
// Kernel 1: 256 CTAs (128 threads, occ 2), item = (batch, 128 q-rows),
// 32 rows per warp. fp16 GEMMs: S = Q16*K16, ctx += P16*V16.
// 4-stage cp.async pipeline, ONE barrier per tile (CUTLASS ordering).
// fp16 unnormalized p -> scratch; per-row inv sums -> g_inv.
// ============================================================================
__global__ void __launch_bounds__(128, 2)
attn_mma_kernel(const float* __restrict__ q,
                float* __restrict__ ctx)
{
    extern __shared__ char smem[];
    const uint32_t sb = smem_u32(smem);
    const uint32_t Q16 = sb + SM_Q16;

    const int t   = threadIdx.x;
    const int wid = t >> 5;            // 0..3
    const int lid = t & 31;

    const float SL = 0.08838834764831845f * 1.4426950408889634f; // scale*log2(e)

    // ldmatrix per-lane base offsets (bytes); warp owns rows [32*wid, 32*wid+32)
    const uint32_t q_off0 = (uint32_t)(wid * 32 + (lid & 15)) * STRB + (uint32_t)(lid >> 4) * 16;
    const uint32_t q_off1 = q_off0 + 16u * STRB;
    const uint32_t k_off  = (uint32_t)((lid & 7) + ((lid >> 4) << 3)) * STRB
                          + (uint32_t)((lid >> 3) & 1) * 16;
    const uint32_t v_off  = (uint32_t)((lid & 7) + (((lid >> 3) & 1) << 3)) * STRB
                          + (uint32_t)(lid >> 4) * 16;

    const int item   = (int)blockIdx.x;
    const int b      = item >> 4;
    const int m_base = (item & 15) * MT;
    const size_t bL  = (size_t)b * L_;
    const float* qb  = q + (bL + m_base) * D_;
    const size_t kvb = bL * D_;

    // stagger tile order across CTAs to decorrelate load phases
    const int start = (int)((blockIdx.x & 3u) << 4);   // 0,16,32,48

    // prologue: prefetch 3 tiles
    #pragma unroll
    for (int pi = 0; pi < 3; ++pi) {
        const int ptile = (start + pi) & (NTILES - 1);
        prefetch_tile(sb + SM_STAGE + (uint32_t)pi * STG_BYTES,
                      kvb + (size_t)(ptile * NT) * D_, t);
        CP_COMMIT();
    }

    // ---- load + convert Q tile (128x128) to fp16: one row per thread ----
    {
        const float4* src = (const float4*)(qb + (size_t)t * D_);
        char* dh = smem + SM_Q16 + t * STRB;
        #pragma unroll
        for (int cc = 0; cc < 16; ++cc) {
            const float4 x0 = src[2 * cc];
            const float4 x1 = src[2 * cc + 1];
            uint4 H;
            H.x = cvt_h2(x0.x, x0.y);
            H.y = cvt_h2(x0.z, x0.w);
            H.z = cvt_h2(x1.x, x1.y);
            H.w = cvt_h2(x1.z, x1.w);
            *(uint4*)(dh + cc * 16) = H;
        }
    }

    float C[2][16][4];
    #pragma unroll
    for (int mf = 0; mf < 2; ++mf)
        #pragma unroll
        for (int f = 0; f < 16; ++f)
            #pragma unroll
            for (int e = 0; e < 4; ++e) C[mf][f][e] = 0.0f;
    float rs[2][2] = {{0.f, 0.f}, {0.f, 0.f}};

    for (int i = 0; i < NTILES; ++i) {
        const int tile = (start + i) & (NTILES - 1);
        const int key0 = tile * NT;
        const uint32_t stg = sb + SM_STAGE + (uint32_t)(i & 3) * STG_BYTES;

        CP_WAIT(2);        // this thread's group for tile i complete
        __syncthreads();   // all threads' tile-i data visible; compute(i-1) done

        if (i + 3 < NTILES) {
            const int ntile = (start + i + 3) & (NTILES - 1);
            prefetch_tile(sb + SM_STAGE + (uint32_t)((i + 3) & 3) * STG_BYTES,
                          kvb + (size_t)(ntile * NT) * D_, t);
        }
        CP_COMMIT();       // empty group at tail keeps accounting uniform

        const uint32_t KHI = stg + STG_K;
        const uint32_t VHI = stg + STG_V;

        // ---- QK: S = Q16*K16, 2 m-frags per warp ----
        float S[2][4][4];
        #pragma unroll
        for (int mf = 0; mf < 2; ++mf)
            #pragma unroll
            for (int f = 0; f < 4; ++f)
                #pragma unroll
                for (int e = 0; e < 4; ++e) S[mf][f][e] = 0.0f;

        #pragma unroll
        for (int ks = 0; ks < 8; ++ks) {
            uint32_t a0[4], a1[4], bh[8];
            LDSM4(a0[0], a0[1], a0[2], a0[3], Q16 + q_off0 + ks * 32);
            LDSM4(a1[0], a1[1], a1[2], a1[3], Q16 + q_off1 + ks * 32);
            #pragma unroll
            for (int j = 0; j < 2; ++j)
                LDSM4(bh[4*j], bh[4*j+1], bh[4*j+2], bh[4*j+3],
                      KHI + k_off + (uint32_t)j * (16 * STRB) + ks * 32);
            #pragma unroll
            for (int j = 0; j < 2; ++j) {
                MMA_F16(S[0][2*j],   a0[0], a0[1], a0[2], a0[3], bh[4*j],   bh[4*j+1]);
                MMA_F16(S[0][2*j+1], a0[0], a0[1], a0[2], a0[3], bh[4*j+2], bh[4*j+3]);
                MMA_F16(S[1][2*j],   a1[0], a1[1], a1[2], a1[3], bh[4*j],   bh[4*j+1]);
                MMA_F16(S[1][2*j+1], a1[0], a1[1], a1[2], a1[3], bh[4*j+2], bh[4*j+3]);
            }
        }

        // ---- exp (1 MUFU each) + fp16 scratch write + pack P16 A-frags ----
        uint32_t PH[2][2][4];
        #pragma unroll
        for (int mf = 0; mf < 2; ++mf) {
            uint32_t* prow = g_pscr
                + (((size_t)(bL + m_base + 32 * wid + 16 * mf + (lid >> 2))) * L_
                   + key0 + 2 * (lid & 3)) / 2;
            #pragma unroll
            for (int f = 0; f < 4; ++f) {
                const float p0 = ex2(S[mf][f][0] * SL);
                const float p1 = ex2(S[mf][f][1] * SL);
                const float p2 = ex2(S[mf][f][2] * SL);
                const float p3 = ex2(S[mf][f][3] * SL);
                rs[mf][0] += p0 + p1;
                rs[mf][1] += p2 + p3;
                const int ks = f >> 1;
                const int hh = (f & 1) * 2;
                PH[mf][ks][hh]     = cvt_h2(p0, p1);
                PH[mf][ks][hh + 1] = cvt_h2(p2, p3);
                prow[4 * f]          = PH[mf][ks][hh];      // row r
                prow[4 * L_ + 4 * f] = PH[mf][ks][hh + 1];  // row r+8
            }
        }

        // ---- PV: ctx += P16*V16 ----
        #pragma unroll
        for (int ks = 0; ks < 2; ++ks) {
            uint32_t vf[32];
            #pragma unroll
            for (int j = 0; j < 8; ++j)
                LDSM4T(vf[4*j], vf[4*j+1], vf[4*j+2], vf[4*j+3],
                       VHI + v_off + (uint32_t)ks * (16 * STRB) + j * 32);
            #pragma unroll
            for (int j = 0; j < 8; ++j) {
                MMA_F16(C[0][2*j],   PH[0][ks][0], PH[0][ks][1], PH[0][ks][2], PH[0][ks][3], vf[4*j],   vf[4*j+1]);
                MMA_F16(C[0][2*j+1], PH[0][ks][0], PH[0][ks][1], PH[0][ks][2], PH[0][ks][3], vf[4*j+2], vf[4*j+3]);
                MMA_F16(C[1][2*j],   PH[1][ks][0], PH[1][ks][1], PH[1][ks][2], PH[1][ks][3], vf[4*j],   vf[4*j+1]);
                MMA_F16(C[1][2*j+1], PH[1][ks][0], PH[1][ks][1], PH[1][ks][2], PH[1][ks][3], vf[4*j+2], vf[4*j+3]);
            }
        }
    }

    // ---- row sums + normalize ctx + store inv sums ----
    #pragma unroll
    for (int mf = 0; mf < 2; ++mf) {
        float r0 = rs[mf][0], r1 = rs[mf][1];
        r0 += __shfl_xor_sync(0xffffffffu, r0, 1);
        r0 += __shfl_xor_sync(0xffffffffu, r0, 2);
        r1 += __shfl_xor_sync(0xffffffffu, r1, 1);
        r1 += __shfl_xor_sync(0xffffffffu, r1, 2);
        const float inv0 = 1.0f / r0;
        const float inv1 = 1.0f / r1;

        const int row0 = m_base + 32 * wid + 16 * mf + (lid >> 2);
        if ((lid & 3) == 0) {
            g_inv[bL + row0]     = inv0;
            g_inv[bL + row0 + 8] = inv1;
        }

        float* crow = ctx + ((size_t)(bL + row0)) * D_ + 2 * (lid & 3);
        #pragma unroll
        for (int f = 0; f < 16; ++f) {
            *(float2*)(crow + 8 * f)          = make_float2(C[mf][f][0] * inv0, C[mf][f][1] * inv0);
            *(float2*)(crow + 8 * D_ + 8 * f) = make_float2(C[mf][f][2] * inv1, C[mf][f][3] * inv1);
        }
    }
}

// ============================================================================
// Kernel 2: streaming normalize: probs = fp16_scratch * inv[row] -> fp32.
// ~57us at 80% DRAM roofline.
// ============================================================================
__global__ void __launch_bounds__(256)
norm_probs_kernel(float* __restrict__ probs)
{
    const size_t rowi = blockIdx.x;
    const int t = threadIdx.x;
    const float inv = g_inv[rowi];

    const uint4 d = ((const uint4*)(g_pscr + rowi * (L_ / 2)))[t];
    float2 f0 = __half22float2(*(const __half2*)&d.x);
    float2 f1 = __half22float2(*(const __half2*)&d.y);
    float2 f2 = __half22float2(*(const __half2*)&d.z);
    float2 f3 = __half22float2(*(const __half2*)&d.w);

    float4 o0, o1;
    o0.x = f0.x * inv; o0.y = f0.y * inv; o0.z = f1.x * inv; o0.w = f1.y * inv;
    o1.x = f2.x * inv; o1.y = f2.y * inv; o1.z = f3.x * inv; o1.w = f3.y * inv;

    float* drow = probs + rowi * (size_t)L_ + t * 8;
    *(float4*)(drow)     = o0;
    *(float4*)(drow + 4) = o1;
}

extern "C" void kernel_launch(void* const* d_in, const int* in_sizes, int n_in,
                              void* d_out, int out_size)
{
    const float* q = (const float*)d_in[0];
    const float* k = (const float*)d_in[1];
    const float* v = (const float*)d_in[2];

    float* out   = (float*)d_out;
    float* ctx   = out;
    float* probs = out + (size_t)B_ * L_ * D_;

    cudaFuncSetAttribute(attn_mma_kernel,
                         cudaFuncAttributeMaxDynamicSharedMemorySize, SMEM_BYTES);

    split_kv_kernel<<<TOT / 4 / 256, 256>>>(k, v);

    attn_mma_kernel<<<NITEMS, 128, SMEM_BYTES>>>(q, ctx);

    norm_probs_kernel<<<B_ * L_, 256>>>(probs);
}